// round 14
// baseline (speedup 1.0000x reference)
#include <cuda_runtime.h>
#include <cuda_bf16.h>

#define TAGS 128
typedef __nv_bfloat162 bf2;

__global__ void __launch_bounds__(TAGS, 1) crf_logz_kernel(
    const float* __restrict__ emissions,     // [B, T, 1, TAGS]
    const int*   __restrict__ token_sizes,   // [B]
    const float* __restrict__ transitions,   // [1, 1, TAGS, TAGS]
    const float* __restrict__ head_t,        // [1, 1, TAGS]
    const float* __restrict__ last_t,        // [1, 1, TAGS]
    float*       __restrict__ out,           // [B, 1]
    int T)
{
    __shared__ __align__(16) __nv_bfloat16 pbuf[2][TAGS];
    __shared__ float wsum[4];

    const int n = threadIdx.x;      // output tag owned by this thread
    const int b = blockIdx.x;       // batch element owned by this CTA
    const int len = token_sizes[b];
    const int Tm1 = T - 1;
    const float* emb = emissions + (size_t)b * T * TAGS;

    // exp(transitions) column n as bf16x2 pairs: T2[i] = (T[2i,n], T[2i+1,n]).
    bf2 T2[TAGS / 2];
#pragma unroll
    for (int i = 0; i < TAGS / 2; ++i)
        T2[i] = __floats2bfloat162_rn(__expf(transitions[(2 * i    ) * TAGS + n]),
                                      __expf(transitions[(2 * i + 1) * TAGS + n]));

    // alpha_0 = head + emissions[0]  ->  p = exp(alpha)  (bf16 storage)
    pbuf[0][n] = __float2bfloat16(__expf(head_t[n] + emb[n]));
    int etot = 0;        // exact integer sum of stripped binary exponents
    int fb = 0;          // live buffer for the tail bookkeeping

// One recurrence step. Structure (per R11/R13 lessons):
//   BAR -> issue all 16 LDS.128 immediately (critical head) ->
//   slot prefetch hook (__VA_ARGS__: 1 LDG + 1 expf + moves) rides the
//   29-cyc LDS-return window and the rt-2 HFMA2 issue gaps ->
//   64 HFMA2 (2 accumulators, stall-free) -> short tail:
//   HADD2 -> HADD(half-lane sel) -> HMUL(bf16 scale) -> STS.b16.
// p[0]'s exponent comes from the first LDS; EV is captured before the
// hook may refresh it.
#define STEP_PF(SRC, DST, EV, ...) do {                                    \
    float _ev = (EV);                                                      \
    __syncthreads();                                                       \
    const uint4* _pd = reinterpret_cast<const uint4*>(&pbuf[SRC][0]);      \
    uint4 _q[16];                                                          \
    _Pragma("unroll")                                                      \
    for (int _i = 0; _i < 16; ++_i) _q[_i] = _pd[_i];                      \
    __VA_ARGS__                                    /* prefetch hook */     \
    int _e = (int)((_q[0].x >> 7) & 255) - 127;    /* bf16 exp of p[0] */  \
    float _sc = __int_as_float((127 - _e) << 23);                          \
    __nv_bfloat16 _Esb = __float2bfloat16(_ev * _sc);                      \
    bf2 _h0 = __float2bfloat162_rn(0.0f);                                  \
    bf2 _h1 = _h0;                                                         \
    _Pragma("unroll")                                                      \
    for (int _i = 0; _i < 16; ++_i) {                                      \
        _h0 = __hfma2(*reinterpret_cast<bf2*>(&_q[_i].x), T2[4*_i    ], _h0);\
        _h1 = __hfma2(*reinterpret_cast<bf2*>(&_q[_i].y), T2[4*_i + 1], _h1);\
        _h0 = __hfma2(*reinterpret_cast<bf2*>(&_q[_i].z), T2[4*_i + 2], _h0);\
        _h1 = __hfma2(*reinterpret_cast<bf2*>(&_q[_i].w), T2[4*_i + 3], _h1);\
    }                                                                      \
    bf2 _s = __hadd2(_h0, _h1);                                            \
    __nv_bfloat16 _f = __hadd(__low2bfloat16(_s), __high2bfloat16(_s));    \
    pbuf[DST][n] = __hmul(_f, _Esb);                                       \
    etot += _e;                                                            \
} while (0)

    // Two-stage emission prefetch with per-slot refresh, now INSIDE the
    // step (in the LDS shadow): E_k consumed at slot k then refreshed from
    // Q_k (4 steps before next use); Q_k reloaded 8 steps ahead.
    int t = 1;
    float E0 = __expf(emb[min(1, Tm1) * TAGS + n]);     // steps t..t+3
    float E1 = __expf(emb[min(2, Tm1) * TAGS + n]);
    float E2 = __expf(emb[min(3, Tm1) * TAGS + n]);
    float E3 = __expf(emb[min(4, Tm1) * TAGS + n]);
    float Q0 = emb[min(5, Tm1) * TAGS + n];             // raw, steps t+4..t+7
    float Q1 = emb[min(6, Tm1) * TAGS + n];
    float Q2 = emb[min(7, Tm1) * TAGS + n];
    float Q3 = emb[min(8, Tm1) * TAGS + n];

    // Fast loop: t+12 <= len implies prefetch rows t+8..t+11 < T: no clamps.
    for (; t + 12 <= len; t += 4) {
        const float* ep = emb + (size_t)(t + 8) * TAGS + n;
        STEP_PF(0, 1, E0, { float _R = ep[0];        E0 = __expf(Q0); Q0 = _R; });
        STEP_PF(1, 0, E1, { float _R = ep[TAGS];     E1 = __expf(Q1); Q1 = _R; });
        STEP_PF(0, 1, E2, { float _R = ep[2 * TAGS]; E2 = __expf(Q2); Q2 = _R; });
        STEP_PF(1, 0, E3, { float _R = ep[3 * TAGS]; E3 = __expf(Q3); Q3 = _R; });
    }
    // Clamped boundary loop (<= 2 iterations).
    for (; t + 4 <= len; t += 4) {
        int tp = t + 8;
        STEP_PF(0, 1, E0, { float _R = emb[min(tp,     Tm1) * TAGS + n]; E0 = __expf(Q0); Q0 = _R; });
        STEP_PF(1, 0, E1, { float _R = emb[min(tp + 1, Tm1) * TAGS + n]; E1 = __expf(Q1); Q1 = _R; });
        STEP_PF(0, 1, E2, { float _R = emb[min(tp + 2, Tm1) * TAGS + n]; E2 = __expf(Q2); Q2 = _R; });
        STEP_PF(1, 0, E3, { float _R = emb[min(tp + 3, Tm1) * TAGS + n]; E3 = __expf(Q3); Q3 = _R; });
    }
    // Tail (0-3 steps); E0..E2 hold exp(em[t..t+2]) by the invariant above.
    if (t < len) { STEP_PF(0, 1, E0, {}); fb = 1; ++t; }
    if (t < len) { STEP_PF(1, 0, E1, {}); fb = 0; ++t; }
    if (t < len) { STEP_PF(0, 1, E2, {}); fb = 1; ++t; }

    // Finalize: out[b] = etot*ln2 + log( sum_n p[n] * exp(last[n]) )  (fp32)
    __syncthreads();
    float v = __bfloat162float(pbuf[fb][n]) * __expf(last_t[n]);
#pragma unroll
    for (int sft = 16; sft > 0; sft >>= 1)
        v += __shfl_xor_sync(0xffffffffu, v, sft);
    if ((n & 31) == 0) wsum[n >> 5] = v;
    __syncthreads();
    if (n == 0)
        out[b] = (float)((double)etot * 0.6931471805599453 +
                         (double)__logf(wsum[0] + wsum[1] + wsum[2] + wsum[3]));
}

extern "C" void kernel_launch(void* const* d_in, const int* in_sizes, int n_in,
                              void* d_out, int out_size) {
    const float* em = (const float*)d_in[0];
    const int*   ts = (const int*)  d_in[1];
    const float* tr = (const float*)d_in[2];
    const float* hd = (const float*)d_in[3];
    const float* lt = (const float*)d_in[4];
    float* out = (float*)d_out;

    int B = in_sizes[1];                       // token_sizes count
    int T = in_sizes[0] / (B * TAGS);          // C == 1

    crf_logz_kernel<<<B, TAGS>>>(em, ts, tr, hd, lt, out, T);
}

// round 16
// speedup vs baseline: 1.0376x; 1.0376x over previous
#include <cuda_runtime.h>
#include <cuda_bf16.h>

#define TAGS 128
typedef __nv_bfloat162 bf2;

__global__ void __launch_bounds__(TAGS, 1) crf_logz_kernel(
    const float* __restrict__ emissions,     // [B, T, 1, TAGS]
    const int*   __restrict__ token_sizes,   // [B]
    const float* __restrict__ transitions,   // [1, 1, TAGS, TAGS]
    const float* __restrict__ head_t,        // [1, 1, TAGS]
    const float* __restrict__ last_t,        // [1, 1, TAGS]
    float*       __restrict__ out,           // [B, 1]
    int T)
{
    __shared__ __align__(16) __nv_bfloat16 pbuf[2][TAGS];
    __shared__ float wsum[4];

    const int n = threadIdx.x;      // output tag owned by this thread
    const int b = blockIdx.x;       // batch element owned by this CTA
    const int len = token_sizes[b];
    const int Tm1 = T - 1;
    const float* emb = emissions + (size_t)b * T * TAGS;

    // exp(transitions) column n as bf16x2 pairs: T2[i] = (T[2i,n], T[2i+1,n]).
    bf2 T2[TAGS / 2];
#pragma unroll
    for (int i = 0; i < TAGS / 2; ++i)
        T2[i] = __floats2bfloat162_rn(__expf(transitions[(2 * i    ) * TAGS + n]),
                                      __expf(transitions[(2 * i + 1) * TAGS + n]));

    // alpha_0 = head + emissions[0]  ->  p = exp(alpha)  (bf16 storage)
    pbuf[0][n] = __float2bfloat16(__expf(head_t[n] + emb[n]));
    int etot = 0;        // exact integer sum of stripped binary exponents

// R13 step (proven fastest + stable): SAME-STEP exponent rescale.
// BAR -> LDS+HFMA2 interleave (ptxas schedule), 2 accumulators
// (reissue spacing 4 cyc = HFMA2 lat, stall-free) -> short tail:
// HADD2 -> HADD(half-lane sel, no PRMT) -> HMUL(bf16 scale) -> STS.b16.
// p[0]'s exponent comes from the first matvec load; scale conversion to
// bf16 rides the HFMA2 issue gaps (consumer ~150 cyc later).
#define STEP_CORE(PSRC, PDST, EV) do {                                     \
    const uint4* _pd = reinterpret_cast<const uint4*>(PSRC);               \
    uint4 _q0 = _pd[0];                                                    \
    int _e = (int)((_q0.x >> 7) & 255) - 127;      /* bf16 exp of p[0] */  \
    float _sc = __int_as_float((127 - _e) << 23);                          \
    __nv_bfloat16 _Esb = __float2bfloat16((EV) * _sc);                     \
    bf2 _h0 = __float2bfloat162_rn(0.0f);                                  \
    bf2 _h1 = _h0;                                                         \
    _h0 = __hfma2(*reinterpret_cast<bf2*>(&_q0.x), T2[0], _h0);            \
    _h1 = __hfma2(*reinterpret_cast<bf2*>(&_q0.y), T2[1], _h1);            \
    _h0 = __hfma2(*reinterpret_cast<bf2*>(&_q0.z), T2[2], _h0);            \
    _h1 = __hfma2(*reinterpret_cast<bf2*>(&_q0.w), T2[3], _h1);            \
    _Pragma("unroll")                                                      \
    for (int _i = 1; _i < 16; ++_i) {                                      \
        uint4 _q = _pd[_i];                        /* 8 p-halves */        \
        _h0 = __hfma2(*reinterpret_cast<bf2*>(&_q.x), T2[4 * _i    ], _h0);\
        _h1 = __hfma2(*reinterpret_cast<bf2*>(&_q.y), T2[4 * _i + 1], _h1);\
        _h0 = __hfma2(*reinterpret_cast<bf2*>(&_q.z), T2[4 * _i + 2], _h0);\
        _h1 = __hfma2(*reinterpret_cast<bf2*>(&_q.w), T2[4 * _i + 3], _h1);\
    }                                                                      \
    bf2 _s = __hadd2(_h0, _h1);                                            \
    __nv_bfloat16 _f = __hadd(__low2bfloat16(_s), __high2bfloat16(_s));    \
    (PDST)[n] = __hmul(_f, _Esb);                                          \
    etot += _e;                                                            \
} while (0)

// Compile-time ping-pong step (fast path).
#define STEP(SRC, DST, EV) do {                                            \
    __syncthreads();                                                       \
    STEP_CORE(&pbuf[SRC][0], pbuf[DST], EV);                               \
} while (0)

// Dynamic-buffer step (tail only; fbv is the live buffer index).
#define STEPD(EV) do {                                                     \
    __syncthreads();                                                       \
    STEP_CORE(&pbuf[fbv][0], pbuf[fbv ^ 1], EV);                           \
    fbv ^= 1;                                                              \
} while (0)

    // Two-stage emission prefetch, unroll 8, per-slot refresh (all work
    // PRE-barrier -- R11/R14 both showed post-barrier placement regresses):
    //   E_k = exp(em[t+k]) consumed at slot k, refreshed from Q_k right
    //   after its step (8 steps before next use); Q_k holds raw em[t+8+k],
    //   reloaded 16 steps ahead.
    int t = 1;
    float E0 = __expf(emb[min(1, Tm1) * TAGS + n]);
    float E1 = __expf(emb[min(2, Tm1) * TAGS + n]);
    float E2 = __expf(emb[min(3, Tm1) * TAGS + n]);
    float E3 = __expf(emb[min(4, Tm1) * TAGS + n]);
    float E4 = __expf(emb[min(5, Tm1) * TAGS + n]);
    float E5 = __expf(emb[min(6, Tm1) * TAGS + n]);
    float E6 = __expf(emb[min(7, Tm1) * TAGS + n]);
    float E7 = __expf(emb[min(8, Tm1) * TAGS + n]);
    float Q0 = emb[min( 9, Tm1) * TAGS + n];
    float Q1 = emb[min(10, Tm1) * TAGS + n];
    float Q2 = emb[min(11, Tm1) * TAGS + n];
    float Q3 = emb[min(12, Tm1) * TAGS + n];
    float Q4 = emb[min(13, Tm1) * TAGS + n];
    float Q5 = emb[min(14, Tm1) * TAGS + n];
    float Q6 = emb[min(15, Tm1) * TAGS + n];
    float Q7 = emb[min(16, Tm1) * TAGS + n];

    // Fast loop: t+24 <= len implies prefetch rows t+16..t+23 <= len-1 < T.
    for (; t + 24 <= len; t += 8) {
        const float* ep = emb + (size_t)(t + 16) * TAGS + n;
        float R0 = ep[0];
        STEP(0, 1, E0);
        float R1 = ep[TAGS];
        E0 = __expf(Q0); Q0 = R0;           // pre-barrier of next step
        STEP(1, 0, E1);
        float R2 = ep[2 * TAGS];
        E1 = __expf(Q1); Q1 = R1;
        STEP(0, 1, E2);
        float R3 = ep[3 * TAGS];
        E2 = __expf(Q2); Q2 = R2;
        STEP(1, 0, E3);
        float R4 = ep[4 * TAGS];
        E3 = __expf(Q3); Q3 = R3;
        STEP(0, 1, E4);
        float R5 = ep[5 * TAGS];
        E4 = __expf(Q4); Q4 = R4;
        STEP(1, 0, E5);
        float R6 = ep[6 * TAGS];
        E5 = __expf(Q5); Q5 = R5;
        STEP(0, 1, E6);
        float R7 = ep[7 * TAGS];
        E6 = __expf(Q6); Q6 = R6;
        STEP(1, 0, E7);
        E7 = __expf(Q7); Q7 = R7;
    }

    // Tail: 0..23 remaining steps. Invariant: E_k = exp(em[t+k]) for
    // t+k <= len-1 region we'll use; Q_k = em[t+8+k] (rows valid whenever
    // consumed, guarded below). Buffer 0 is live (even flips per group).
    int fbv = 0;
    int rem = len - t;
    // Pre-issue phase-3 boundary loads (rows t+16..t+22, all < len <= T),
    // covered by the ~16 steps of phases 1-2.
    float P0 = 0.f, P1 = 0.f, P2 = 0.f, P3 = 0.f, P4 = 0.f, P5 = 0.f, P6 = 0.f;
    if (rem > 16) P0 = emb[(size_t)(t + 16) * TAGS + n];
    if (rem > 17) P1 = emb[(size_t)(t + 17) * TAGS + n];
    if (rem > 18) P2 = emb[(size_t)(t + 18) * TAGS + n];
    if (rem > 19) P3 = emb[(size_t)(t + 19) * TAGS + n];
    if (rem > 20) P4 = emb[(size_t)(t + 20) * TAGS + n];
    if (rem > 21) P5 = emb[(size_t)(t + 21) * TAGS + n];
    if (rem > 22) P6 = emb[(size_t)(t + 22) * TAGS + n];
    // Phase 1: ready E0..E7.
    if (rem >  0) STEPD(E0);
    if (rem >  1) STEPD(E1);
    if (rem >  2) STEPD(E2);
    if (rem >  3) STEPD(E3);
    if (rem >  4) STEPD(E4);
    if (rem >  5) STEPD(E5);
    if (rem >  6) STEPD(E6);
    if (rem >  7) STEPD(E7);
    // Phase 2: exp of already-loaded Q0..Q7.
    if (rem >  8) STEPD(__expf(Q0));
    if (rem >  9) STEPD(__expf(Q1));
    if (rem > 10) STEPD(__expf(Q2));
    if (rem > 11) STEPD(__expf(Q3));
    if (rem > 12) STEPD(__expf(Q4));
    if (rem > 13) STEPD(__expf(Q5));
    if (rem > 14) STEPD(__expf(Q6));
    if (rem > 15) STEPD(__expf(Q7));
    // Phase 3: pre-issued boundary loads P0..P6.
    if (rem > 16) STEPD(__expf(P0));
    if (rem > 17) STEPD(__expf(P1));
    if (rem > 18) STEPD(__expf(P2));
    if (rem > 19) STEPD(__expf(P3));
    if (rem > 20) STEPD(__expf(P4));
    if (rem > 21) STEPD(__expf(P5));
    if (rem > 22) STEPD(__expf(P6));

    // Finalize: out[b] = etot*ln2 + log( sum_n p[n] * exp(last[n]) )  (fp32)
    __syncthreads();
    float v = __bfloat162float(pbuf[fbv][n]) * __expf(last_t[n]);
#pragma unroll
    for (int sft = 16; sft > 0; sft >>= 1)
        v += __shfl_xor_sync(0xffffffffu, v, sft);
    if ((n & 31) == 0) wsum[n >> 5] = v;
    __syncthreads();
    if (n == 0)
        out[b] = (float)((double)etot * 0.6931471805599453 +
                         (double)__logf(wsum[0] + wsum[1] + wsum[2] + wsum[3]));
}

extern "C" void kernel_launch(void* const* d_in, const int* in_sizes, int n_in,
                              void* d_out, int out_size) {
    const float* em = (const float*)d_in[0];
    const int*   ts = (const int*)  d_in[1];
    const float* tr = (const float*)d_in[2];
    const float* hd = (const float*)d_in[3];
    const float* lt = (const float*)d_in[4];
    float* out = (float*)d_out;

    int B = in_sizes[1];                       // token_sizes count
    int T = in_sizes[0] / (B * TAGS);          // C == 1

    crf_logz_kernel<<<B, TAGS>>>(em, ts, tr, hd, lt, out, T);
}

// round 17
// speedup vs baseline: 1.0678x; 1.0291x over previous
#include <cuda_runtime.h>
#include <cuda_bf16.h>

#define TAGS 128
typedef __nv_bfloat162 bf2;

__global__ void __launch_bounds__(TAGS, 1) crf_logz_kernel(
    const float* __restrict__ emissions,     // [B, T, 1, TAGS]
    const int*   __restrict__ token_sizes,   // [B]
    const float* __restrict__ transitions,   // [1, 1, TAGS, TAGS]
    const float* __restrict__ head_t,        // [1, 1, TAGS]
    const float* __restrict__ last_t,        // [1, 1, TAGS]
    float*       __restrict__ out,           // [B, 1]
    int T)
{
    __shared__ __align__(16) __nv_bfloat16 pbuf[2][TAGS];
    __shared__ float wsum[4];

    const int n = threadIdx.x;      // output tag owned by this thread
    const int b = blockIdx.x;       // batch element owned by this CTA
    const int len = token_sizes[b];
    const int Tm1 = T - 1;
    const float* emb = emissions + (size_t)b * T * TAGS;

    // exp(transitions) column n as bf16x2 pairs: T2[i] = (T[2i,n], T[2i+1,n]).
    bf2 T2[TAGS / 2];
#pragma unroll
    for (int i = 0; i < TAGS / 2; ++i)
        T2[i] = __floats2bfloat162_rn(__expf(transitions[(2 * i    ) * TAGS + n]),
                                      __expf(transitions[(2 * i + 1) * TAGS + n]));

    // alpha_0 = head + emissions[0]  ->  p = exp(alpha)  (bf16 storage)
    pbuf[0][n] = __float2bfloat16(__expf(head_t[n] + emb[n]));
    int etot = 0;        // exact integer sum of stripped binary exponents

// Pre-barrier fold of an exp'd emission into integer form:
//   EB = bits(bf16(E)) + (127<<7)
// so the post-barrier scale E*2^{-e} is the EXACT integer subtract
//   Esb_bits = EB - (q0.x & 0x7F80)        (e_field<<7 of p[0])
// -- one LOP3 + one IADD3 instead of FMUL + cvt. Bit-identical result
// (power-of-2 scaling commutes with bf16 rounding); e range [-10,17] is
// far from exponent-field wrap.
#define EFOLD(EV) ((unsigned)__bfloat16_as_ushort(__float2bfloat16(EV)) + (127u << 7))

// One recurrence step core. BAR handled by wrappers. Post-barrier body:
// LDS+HFMA2 interleave (ptxas schedule), first chunk via HMUL2 (no
// zero-init), 2 accumulators (reissue spacing 4 cyc = HFMA2 lat) ->
// HADD2 -> HADD(half-lane sel) -> HMUL(int-built bf16 scale) -> STS.b16.
#define STEP_CORE(PSRC, PDST, EB) do {                                     \
    const uint4* _pd = reinterpret_cast<const uint4*>(PSRC);               \
    uint4 _q0 = _pd[0];                                                    \
    unsigned _ef = _q0.x & 0x7F80u;                /* e_field<<7 */        \
    __nv_bfloat16 _Esb = __ushort_as_bfloat16((unsigned short)((EB) - _ef)); \
    etot += (int)(_ef >> 7) - 127;                                         \
    bf2 _h0 = __hmul2(*reinterpret_cast<bf2*>(&_q0.x), T2[0]);             \
    bf2 _h1 = __hmul2(*reinterpret_cast<bf2*>(&_q0.y), T2[1]);             \
    _h0 = __hfma2(*reinterpret_cast<bf2*>(&_q0.z), T2[2], _h0);            \
    _h1 = __hfma2(*reinterpret_cast<bf2*>(&_q0.w), T2[3], _h1);            \
    _Pragma("unroll")                                                      \
    for (int _i = 1; _i < 16; ++_i) {                                      \
        uint4 _q = _pd[_i];                        /* 8 p-halves */        \
        _h0 = __hfma2(*reinterpret_cast<bf2*>(&_q.x), T2[4 * _i    ], _h0);\
        _h1 = __hfma2(*reinterpret_cast<bf2*>(&_q.y), T2[4 * _i + 1], _h1);\
        _h0 = __hfma2(*reinterpret_cast<bf2*>(&_q.z), T2[4 * _i + 2], _h0);\
        _h1 = __hfma2(*reinterpret_cast<bf2*>(&_q.w), T2[4 * _i + 3], _h1);\
    }                                                                      \
    bf2 _s = __hadd2(_h0, _h1);                                            \
    __nv_bfloat16 _f = __hadd(__low2bfloat16(_s), __high2bfloat16(_s));    \
    (PDST)[n] = __hmul(_f, _Esb);                                          \
} while (0)

// Compile-time ping-pong step (fast path); EBV precomputed pre-barrier.
#define STEP(SRC, DST, EBV) do {                                           \
    __syncthreads();                                                       \
    STEP_CORE(&pbuf[SRC][0], pbuf[DST], EBV);                              \
} while (0)

// Dynamic-buffer step (tail only); EV folded pre-barrier.
#define STEPD(EV) do {                                                     \
    unsigned _eb = EFOLD(EV);                                              \
    __syncthreads();                                                       \
    STEP_CORE(&pbuf[fbv][0], pbuf[fbv ^ 1], _eb);                          \
    fbv ^= 1;                                                              \
} while (0)

    // Two-stage emission prefetch, unroll 8, per-slot refresh (all work
    // PRE-barrier): E_k = exp(em[t+k]) folded to EB_k, consumed at slot k,
    // refreshed from Q_k right after its step (8 steps before next use);
    // Q_k holds raw em[t+8+k], reloaded 16 steps ahead.
    int t = 1;
    float E0 = __expf(emb[min(1, Tm1) * TAGS + n]);
    float E1 = __expf(emb[min(2, Tm1) * TAGS + n]);
    float E2 = __expf(emb[min(3, Tm1) * TAGS + n]);
    float E3 = __expf(emb[min(4, Tm1) * TAGS + n]);
    float E4 = __expf(emb[min(5, Tm1) * TAGS + n]);
    float E5 = __expf(emb[min(6, Tm1) * TAGS + n]);
    float E6 = __expf(emb[min(7, Tm1) * TAGS + n]);
    float E7 = __expf(emb[min(8, Tm1) * TAGS + n]);
    float Q0 = emb[min( 9, Tm1) * TAGS + n];
    float Q1 = emb[min(10, Tm1) * TAGS + n];
    float Q2 = emb[min(11, Tm1) * TAGS + n];
    float Q3 = emb[min(12, Tm1) * TAGS + n];
    float Q4 = emb[min(13, Tm1) * TAGS + n];
    float Q5 = emb[min(14, Tm1) * TAGS + n];
    float Q6 = emb[min(15, Tm1) * TAGS + n];
    float Q7 = emb[min(16, Tm1) * TAGS + n];

    // Fast loop: t+24 <= len implies prefetch rows t+16..t+23 <= len-1 < T.
    for (; t + 24 <= len; t += 8) {
        const float* ep = emb + (size_t)(t + 16) * TAGS + n;
        float R0 = ep[0];
        STEP(0, 1, EFOLD(E0));
        float R1 = ep[TAGS];
        E0 = __expf(Q0); Q0 = R0;           // pre-barrier of next step
        STEP(1, 0, EFOLD(E1));
        float R2 = ep[2 * TAGS];
        E1 = __expf(Q1); Q1 = R1;
        STEP(0, 1, EFOLD(E2));
        float R3 = ep[3 * TAGS];
        E2 = __expf(Q2); Q2 = R2;
        STEP(1, 0, EFOLD(E3));
        float R4 = ep[4 * TAGS];
        E3 = __expf(Q3); Q3 = R3;
        STEP(0, 1, EFOLD(E4));
        float R5 = ep[5 * TAGS];
        E4 = __expf(Q4); Q4 = R4;
        STEP(1, 0, EFOLD(E5));
        float R6 = ep[6 * TAGS];
        E5 = __expf(Q5); Q5 = R5;
        STEP(0, 1, EFOLD(E6));
        float R7 = ep[7 * TAGS];
        E6 = __expf(Q6); Q6 = R6;
        STEP(1, 0, EFOLD(E7));
        E7 = __expf(Q7); Q7 = R7;
    }

    // Tail: 0..23 remaining steps. Buffer 0 live (even flips per group).
    int fbv = 0;
    int rem = len - t;
    // Pre-issue phase-3 boundary loads (rows t+16..t+22, all < len <= T),
    // covered by the ~16 steps of phases 1-2.
    float P0 = 0.f, P1 = 0.f, P2 = 0.f, P3 = 0.f, P4 = 0.f, P5 = 0.f, P6 = 0.f;
    if (rem > 16) P0 = emb[(size_t)(t + 16) * TAGS + n];
    if (rem > 17) P1 = emb[(size_t)(t + 17) * TAGS + n];
    if (rem > 18) P2 = emb[(size_t)(t + 18) * TAGS + n];
    if (rem > 19) P3 = emb[(size_t)(t + 19) * TAGS + n];
    if (rem > 20) P4 = emb[(size_t)(t + 20) * TAGS + n];
    if (rem > 21) P5 = emb[(size_t)(t + 21) * TAGS + n];
    if (rem > 22) P6 = emb[(size_t)(t + 22) * TAGS + n];
    // Phase 1: ready E0..E7.
    if (rem >  0) STEPD(E0);
    if (rem >  1) STEPD(E1);
    if (rem >  2) STEPD(E2);
    if (rem >  3) STEPD(E3);
    if (rem >  4) STEPD(E4);
    if (rem >  5) STEPD(E5);
    if (rem >  6) STEPD(E6);
    if (rem >  7) STEPD(E7);
    // Phase 2: exp of already-loaded Q0..Q7.
    if (rem >  8) STEPD(__expf(Q0));
    if (rem >  9) STEPD(__expf(Q1));
    if (rem > 10) STEPD(__expf(Q2));
    if (rem > 11) STEPD(__expf(Q3));
    if (rem > 12) STEPD(__expf(Q4));
    if (rem > 13) STEPD(__expf(Q5));
    if (rem > 14) STEPD(__expf(Q6));
    if (rem > 15) STEPD(__expf(Q7));
    // Phase 3: pre-issued boundary loads P0..P6.
    if (rem > 16) STEPD(__expf(P0));
    if (rem > 17) STEPD(__expf(P1));
    if (rem > 18) STEPD(__expf(P2));
    if (rem > 19) STEPD(__expf(P3));
    if (rem > 20) STEPD(__expf(P4));
    if (rem > 21) STEPD(__expf(P5));
    if (rem > 22) STEPD(__expf(P6));

    // Finalize: out[b] = etot*ln2 + log( sum_n p[n] * exp(last[n]) )  (fp32)
    __syncthreads();
    float v = __bfloat162float(pbuf[fbv][n]) * __expf(last_t[n]);
#pragma unroll
    for (int sft = 16; sft > 0; sft >>= 1)
        v += __shfl_xor_sync(0xffffffffu, v, sft);
    if ((n & 31) == 0) wsum[n >> 5] = v;
    __syncthreads();
    if (n == 0)
        out[b] = (float)((double)etot * 0.6931471805599453 +
                         (double)__logf(wsum[0] + wsum[1] + wsum[2] + wsum[3]));
}

extern "C" void kernel_launch(void* const* d_in, const int* in_sizes, int n_in,
                              void* d_out, int out_size) {
    const float* em = (const float*)d_in[0];
    const int*   ts = (const int*)  d_in[1];
    const float* tr = (const float*)d_in[2];
    const float* hd = (const float*)d_in[3];
    const float* lt = (const float*)d_in[4];
    float* out = (float*)d_out;

    int B = in_sizes[1];                       // token_sizes count
    int T = in_sizes[0] / (B * TAGS);          // C == 1

    crf_logz_kernel<<<B, TAGS>>>(em, ts, tr, hd, lt, out, T);
}